// round 11
// baseline (speedup 1.0000x reference)
#include <cuda_runtime.h>
#include <math.h>
#include <stdint.h>

#define BSZ    2
#define LSEQ   2048
#define DMODEL 512
#define DINNER 1024
#define DSTATE 16
#define DTRANK 32
#define DCONV  4
#define NROWS  (BSZ*LSEQ)          // 4096
#define DBLC   (DTRANK + 2*DSTATE) // 64
#define NCH    8                   // scan chunks per sequence
#define CL     (LSEQ/NCH)          // 256 steps per chunk

// ---------------- scratch (device globals; no allocs allowed) ----------------
__device__ float g_xz  [NROWS * 2 * DINNER];
__device__ float g_xc  [NROWS * DINNER];
__device__ float g_dbl [NROWS * DBLC];
__device__ float g_dt  [NROWS * DINNER];
__device__ float g_y   [NROWS * DINNER];
__device__ float g_hend[BSZ*NCH*DINNER*DSTATE];
__device__ float g_pend[BSZ*NCH*DINNER*DSTATE];

__device__ __forceinline__ float f2tf32(float x) {
    uint32_t u;
    asm("cvt.rna.tf32.f32 %0, %1;" : "=r"(u) : "f"(x));
    return __uint_as_float(u);
}

__device__ __forceinline__ void mma_tf32(float c[4], const uint32_t a[4],
                                         const uint32_t b[2]) {
    asm volatile(
        "mma.sync.aligned.m16n8k8.row.col.f32.tf32.tf32.f32 "
        "{%0,%1,%2,%3}, {%4,%5,%6,%7}, {%8,%9}, {%0,%1,%2,%3};"
        : "+f"(c[0]), "+f"(c[1]), "+f"(c[2]), "+f"(c[3])
        : "r"(a[0]), "r"(a[1]), "r"(a[2]), "r"(a[3]), "r"(b[0]), "r"(b[1]));
}

__device__ __forceinline__ void cp_async16(uint32_t dst, const void* src) {
    asm volatile("cp.async.cg.shared.global [%0], [%1], 16;" :: "r"(dst), "l"(src));
}
#define CP_COMMIT() asm volatile("cp.async.commit_group;" ::: "memory")
#define CP_WAIT0()  asm volatile("cp.async.wait_group 0;"  ::: "memory")

// Old-style conflict-free XOR swizzle (used by the fused xproj kernel only).
template<int LD>
__device__ __forceinline__ int swz(int c, int m) {
    return c*LD + (m ^ ((c & 3) << 3) ^ (((c >> 2) & 7) << 2));
}

// ---------------------------------------------------------------------------
// cp.async double-buffered TF32 warp-MMA GEMM.
// C[M,N] = A[M,K](lda) @ W[K,N](ldb), both row-major, fp32 in gmem.
// A staged as [m][k] LDA=36 (fragment banks 4g+q, distinct); B staged as
// [k][n] LDB=BN+8 (fragment banks 8q+g, distinct). fp32 bits fed to tf32 MMA
// (HW truncation). MODE 0: C=D. 1: C=D+RES. 2: C=softplus(D+bias).
// ---------------------------------------------------------------------------
template<int BM, int BN, int WARPS_M, int WARPS_N, int MODE>
__global__ void __launch_bounds__(WARPS_M*WARPS_N*32)
mma_gemm(const float* __restrict__ A, int lda,
         const float* __restrict__ W, int ldb,
         const float* __restrict__ RES,
         const float* __restrict__ bias,
         float* __restrict__ C, int N, int K)
{
    constexpr int BK = 32;
    constexpr int LDA = BK + 4;      // 36
    constexpr int LDB = BN + 8;      // 136 for BN=128
    constexpr int THREADS = WARPS_M*WARPS_N*32;
    constexpr int WM = BM/WARPS_M, WN = BN/WARPS_N;
    constexpr int MT = WM/16, NT = WN/8;
    constexpr int A_CH = (BM*(BK/4)) / THREADS;   // 16B chunks per thread
    constexpr int B_CH = ((BK*BN)/4) / THREADS;
    constexpr int ASZ = BM*LDA, BSZF = BK*LDB;

    extern __shared__ float sm[];
    float* Abuf[2] = { sm, sm + ASZ };
    float* Bbuf[2] = { sm + 2*ASZ, sm + 2*ASZ + BSZF };

    const int tid  = threadIdx.x;
    const int wid  = tid >> 5;
    const int lane = tid & 31;
    const int g    = lane >> 2;
    const int q    = lane & 3;
    const int wm0  = (wid % WARPS_M) * WM;
    const int wn0  = (wid / WARPS_M) * WN;
    const int bm   = blockIdx.y * BM;
    const int bn   = blockIdx.x * BN;

    const uint32_t sA0 = (uint32_t)__cvta_generic_to_shared(Abuf[0]);
    const uint32_t sA1 = (uint32_t)__cvta_generic_to_shared(Abuf[1]);
    const uint32_t sB0 = (uint32_t)__cvta_generic_to_shared(Bbuf[0]);
    const uint32_t sB1 = (uint32_t)__cvta_generic_to_shared(Bbuf[1]);

    float acc[MT][NT][4];
    #pragma unroll
    for (int i = 0; i < MT; i++)
        #pragma unroll
        for (int j = 0; j < NT; j++)
            #pragma unroll
            for (int v = 0; v < 4; v++) acc[i][j][v] = 0.f;

    auto load_tile = [&](int st, int k0) {
        uint32_t ab = st ? sA1 : sA0;
        uint32_t bb = st ? sB1 : sB0;
        #pragma unroll
        for (int i = 0; i < A_CH; i++) {
            int idx = tid + i*THREADS;
            int r = idx >> 3, c4 = idx & 7;
            cp_async16(ab + (uint32_t)(r*LDA + c4*4)*4,
                       A + (long)(bm + r)*lda + k0 + c4*4);
        }
        #pragma unroll
        for (int i = 0; i < B_CH; i++) {
            int idx = tid + i*THREADS;
            int kr = idx / (BN/4), nc4 = idx % (BN/4);
            cp_async16(bb + (uint32_t)(kr*LDB + nc4*4)*4,
                       W + (long)(k0 + kr)*ldb + bn + nc4*4);
        }
        CP_COMMIT();
    };

    load_tile(0, 0);

    for (int k0 = 0; k0 < K; k0 += BK) {
        const int st = (k0 / BK) & 1;
        const float* As = Abuf[st];
        const float* Bs = Bbuf[st];

        CP_WAIT0();
        __syncthreads();
        if (k0 + BK < K) load_tile(st ^ 1, k0 + BK);

        #pragma unroll
        for (int kk = 0; kk < 4; kk++) {
            const int kb = kk*8;
            uint32_t ah[MT][4], bh[NT][2];
            #pragma unroll
            for (int i = 0; i < MT; i++) {
                int m0 = wm0 + i*16 + g;
                ah[i][0] = __float_as_uint(As[(m0    )*LDA + kb + q    ]);
                ah[i][1] = __float_as_uint(As[(m0 + 8)*LDA + kb + q    ]);
                ah[i][2] = __float_as_uint(As[(m0    )*LDA + kb + q + 4]);
                ah[i][3] = __float_as_uint(As[(m0 + 8)*LDA + kb + q + 4]);
            }
            #pragma unroll
            for (int j = 0; j < NT; j++) {
                int n0 = wn0 + j*8 + g;
                bh[j][0] = __float_as_uint(Bs[(kb + q    )*LDB + n0]);
                bh[j][1] = __float_as_uint(Bs[(kb + q + 4)*LDB + n0]);
            }
            #pragma unroll
            for (int i = 0; i < MT; i++)
                #pragma unroll
                for (int j = 0; j < NT; j++)
                    mma_tf32(acc[i][j], ah[i], bh[j]);
        }
        __syncthreads();
    }

    // epilogue (mapping identical to verified R5/R8 kernels)
    #pragma unroll
    for (int i = 0; i < MT; i++) {
        #pragma unroll
        for (int half = 0; half < 2; half++) {
            int row = bm + wm0 + i*16 + g + half*8;
            #pragma unroll
            for (int j = 0; j < NT; j++) {
                int col = bn + wn0 + j*8 + 2*q;
                float v0 = acc[i][j][half*2 + 0];
                float v1 = acc[i][j][half*2 + 1];
                long base = (long)row*N + col;
                if (MODE == 1) {
                    v0 += RES[base]; v1 += RES[base + 1];
                } else if (MODE == 2) {
                    v0 += bias[col]; v1 += bias[col + 1];
                    v0 = (v0 > 20.f) ? v0 : log1pf(expf(v0));
                    v1 = (v1 > 20.f) ? v1 : log1pf(expf(v1));
                }
                *(float2*)(C + base) = make_float2(v0, v1);
            }
        }
    }
}

// ---------------------------------------------------------------------------
// Fused conv+silu+xproj (unchanged from passing R8/R9 kernel).
// ---------------------------------------------------------------------------
__global__ void __launch_bounds__(128)
xproj_conv_kernel(const float* __restrict__ conv_w,
                  const float* __restrict__ conv_b,
                  const float* __restrict__ Wx)
{
    constexpr int BM = 64, BN = 64, BK = 32;
    constexpr int MT = 2, NT = 4;

    __shared__ float As[BK*BM];
    __shared__ float Bs[BK*BN];

    const int tid  = threadIdx.x;
    const int wid  = tid >> 5;
    const int lane = tid & 31;
    const int g    = lane >> 2;
    const int q    = lane & 3;
    const int wm0  = (wid & 1) * 32;
    const int wn0  = (wid >> 1) * 32;
    const int bm   = blockIdx.x * BM;

    float acc[MT][NT][4];
    #pragma unroll
    for (int i = 0; i < MT; i++)
        #pragma unroll
        for (int j = 0; j < NT; j++)
            #pragma unroll
            for (int v = 0; v < 4; v++) acc[i][j][v] = 0.f;

    for (int k0 = 0; k0 < DINNER; k0 += BK) {
        #pragma unroll
        for (int i = 0; i < 4; i++) {
            int idx = tid + i*128;
            int r = idx >> 3, c4 = idx & 7;
            int m = bm + r;
            int l = m & (LSEQ - 1);
            int k = k0 + c4*4;

            float tv[4][4];
            #pragma unroll
            for (int j = 0; j < 4; j++) {
                float4 t = make_float4(0.f, 0.f, 0.f, 0.f);
                if (l - 3 + j >= 0)
                    t = *(const float4*)(g_xz + (long)(m - 3 + j)*(2*DINNER) + k);
                tv[j][0] = t.x; tv[j][1] = t.y; tv[j][2] = t.z; tv[j][3] = t.w;
            }
            float4 cb = *(const float4*)(conv_b + k);
            float cbv[4] = {cb.x, cb.y, cb.z, cb.w};
            float xo[4];
            #pragma unroll
            for (int cc = 0; cc < 4; cc++) {
                float4 w = *(const float4*)(conv_w + (k + cc)*DCONV);
                float a = cbv[cc] + w.x*tv[0][cc] + w.y*tv[1][cc]
                                  + w.z*tv[2][cc] + w.w*tv[3][cc];
                float sig = 1.f / (1.f + __expf(-a));
                xo[cc] = a * sig;
                As[swz<BM>(c4*4 + cc, r)] = f2tf32(xo[cc]);
            }
            *(float4*)(g_xc + (long)m*DINNER + k) =
                make_float4(xo[0], xo[1], xo[2], xo[3]);
        }
        #pragma unroll
        for (int i = 0; i < 4; i++) {
            int idx = tid + i*128;
            int kr = idx >> 4, nc4 = idx & 15;
            float4 v = *(const float4*)(Wx + (long)(k0 + kr)*DBLC + nc4*4);
            float4 t;
            t.x = f2tf32(v.x); t.y = f2tf32(v.y);
            t.z = f2tf32(v.z); t.w = f2tf32(v.w);
            *(float4*)(Bs + swz<BN>(kr, nc4*4)) = t;
        }
        __syncthreads();

        #pragma unroll
        for (int kk = 0; kk < 4; kk++) {
            const int kb = kk*8;
            uint32_t ah[MT][4], bh[NT][2];
            #pragma unroll
            for (int i = 0; i < MT; i++) {
                int m0 = wm0 + i*16 + g;
                ah[i][0] = __float_as_uint(As[swz<BM>(kb+q,   m0    )]);
                ah[i][1] = __float_as_uint(As[swz<BM>(kb+q,   m0 + 8)]);
                ah[i][2] = __float_as_uint(As[swz<BM>(kb+q+4, m0    )]);
                ah[i][3] = __float_as_uint(As[swz<BM>(kb+q+4, m0 + 8)]);
            }
            #pragma unroll
            for (int j = 0; j < NT; j++) {
                int n0 = wn0 + j*8 + g;
                bh[j][0] = __float_as_uint(Bs[swz<BN>(kb+q,   n0)]);
                bh[j][1] = __float_as_uint(Bs[swz<BN>(kb+q+4, n0)]);
            }
            #pragma unroll
            for (int i = 0; i < MT; i++)
                #pragma unroll
                for (int j = 0; j < NT; j++)
                    mma_tf32(acc[i][j], ah[i], bh[j]);
        }
        __syncthreads();
    }

    #pragma unroll
    for (int i = 0; i < MT; i++) {
        #pragma unroll
        for (int half = 0; half < 2; half++) {
            int row = bm + wm0 + i*16 + g + half*8;
            #pragma unroll
            for (int j = 0; j < NT; j++) {
                int col = wn0 + j*8 + 2*q;
                *(float2*)(g_dbl + (long)row*DBLC + col) =
                    make_float2(acc[i][j][half*2 + 0], acc[i][j][half*2 + 1]);
            }
        }
    }
}

// ---------------------------------------------------------------------------
// Chunked parallel scan. Pass 1: per-chunk local scan from h=0.
// gid -> s=gid&15, d=(gid>>4)&1023, ch=(gid>>14)&7, b=gid>>17.
// ---------------------------------------------------------------------------
__global__ void __launch_bounds__(128) scan_part1(const float* __restrict__ A_log)
{
    int gid = blockIdx.x * 128 + threadIdx.x;
    int s  = gid & 15;
    int d  = (gid >> 4) & 1023;
    int ch = (gid >> 14) & 7;
    int b  = gid >> 17;

    const float A = -expf(A_log[d*DSTATE + s]);
    float h = 0.f, P = 1.f;

    int row = b*LSEQ + ch*CL;
    for (int t0 = 0; t0 < CL; t0 += 4, row += 4) {
        float dtv[4], xv[4], Bv[4], Cv[4];
        #pragma unroll
        for (int u = 0; u < 4; u++) {
            int r = row + u;
            dtv[u] = g_dt [(long)r*DINNER + d];
            xv [u] = g_xc [(long)r*DINNER + d];
            Bv [u] = g_dbl[(long)r*DBLC + DTRANK + s];
            Cv [u] = g_dbl[(long)r*DBLC + DTRANK + DSTATE + s];
        }
        float p[4];
        #pragma unroll
        for (int u = 0; u < 4; u++) {
            float dA = __expf(dtv[u] * A);
            h = h * dA + (dtv[u] * xv[u]) * Bv[u];
            P *= dA;
            p[u] = h * Cv[u];
        }
        #pragma unroll
        for (int off = 8; off; off >>= 1) {
            #pragma unroll
            for (int u = 0; u < 4; u++)
                p[u] += __shfl_xor_sync(0xffffffffu, p[u], off);
        }
        if (s == 0) {
            #pragma unroll
            for (int u = 0; u < 4; u++)
                g_y[(long)(row + u)*DINNER + d] = p[u];
        }
    }
    long idx = ((long)((b*NCH + ch)*DINNER + d))*DSTATE + s;
    g_hend[idx] = h;
    g_pend[idx] = P;
}

// Pass 2 (combine folded in): each thread chains predecessor chunk states,
// then adds correction C.(Q_t o h_in) and applies D-skip + silu(z) gating.
__global__ void __launch_bounds__(128) scan_part3(const float* __restrict__ A_log,
                                                  const float* __restrict__ Dvec)
{
    int gid = blockIdx.x * 128 + threadIdx.x;
    int s  = gid & 15;
    int d  = (gid >> 4) & 1023;
    int ch = (gid >> 14) & 7;   // uniform within a block
    int b  = gid >> 17;

    const float A  = -expf(A_log[d*DSTATE + s]);
    const float Dv = Dvec[d];

    float hin = 0.f;
    for (int c = 0; c < ch; c++) {
        long idx = ((long)((b*NCH + c)*DINNER + d))*DSTATE + s;
        hin = g_pend[idx] * hin + g_hend[idx];
    }

    float P = 1.f;
    int row = b*LSEQ + ch*CL;
    for (int t0 = 0; t0 < CL; t0 += 4, row += 4) {
        float dtv[4], Cv[4];
        #pragma unroll
        for (int u = 0; u < 4; u++) {
            int r = row + u;
            dtv[u] = g_dt [(long)r*DINNER + d];
            Cv [u] = g_dbl[(long)r*DBLC + DTRANK + DSTATE + s];
        }
        float p[4];
        #pragma unroll
        for (int u = 0; u < 4; u++) {
            P *= __expf(dtv[u] * A);
            p[u] = (P * hin) * Cv[u];
        }
        #pragma unroll
        for (int off = 8; off; off >>= 1) {
            #pragma unroll
            for (int u = 0; u < 4; u++)
                p[u] += __shfl_xor_sync(0xffffffffu, p[u], off);
        }
        if (s == 0) {
            #pragma unroll
            for (int u = 0; u < 4; u++) {
                int r = row + u;
                float y  = g_y[(long)r*DINNER + d] + p[u];
                float xv = g_xc[(long)r*DINNER + d];
                float zv = g_xz[(long)r*(2*DINNER) + DINNER + d];
                float sig = 1.f / (1.f + __expf(-zv));
                g_y[(long)r*DINNER + d] = (y + xv*Dv) * (zv * sig);
            }
        }
    }
}

// ---------------------------------------------------------------------------
// LayerNorm over rows of 512 (in-place)
// ---------------------------------------------------------------------------
__global__ void ln_kernel(float* __restrict__ out,
                          const float* __restrict__ gamma,
                          const float* __restrict__ beta)
{
    int row = blockIdx.x;
    int t   = threadIdx.x;
    float v0 = out[(long)row*DMODEL + t];
    float v1 = out[(long)row*DMODEL + 256 + t];

    float s = v0 + v1;
    float qq = v0*v0 + v1*v1;
    #pragma unroll
    for (int o = 16; o; o >>= 1) {
        s  += __shfl_xor_sync(0xffffffffu, s, o);
        qq += __shfl_xor_sync(0xffffffffu, qq, o);
    }
    __shared__ float s1[8], s2[8];
    int wid = t >> 5, lane = t & 31;
    if (lane == 0) { s1[wid] = s; s2[wid] = qq; }
    __syncthreads();
    if (t == 0) {
        float ts = 0.f, tq = 0.f;
        #pragma unroll
        for (int i = 0; i < 8; i++) { ts += s1[i]; tq += s2[i]; }
        float mu = ts / DMODEL;
        s1[0] = mu;
        s2[0] = tq / DMODEL - mu*mu;
    }
    __syncthreads();
    float mu  = s1[0];
    float inv = rsqrtf(s2[0] + 1e-5f);
    out[(long)row*DMODEL + t]       = (v0 - mu) * inv * gamma[t]       + beta[t];
    out[(long)row*DMODEL + 256 + t] = (v1 - mu) * inv * gamma[256 + t] + beta[256 + t];
}

// ---------------------------------------------------------------------------
extern "C" void kernel_launch(void* const* d_in, const int* in_sizes, int n_in,
                              void* d_out, int out_size)
{
    const float* x      = (const float*)d_in[0];
    const float* W_in   = (const float*)d_in[1];
    const float* conv_w = (const float*)d_in[2];
    const float* conv_b = (const float*)d_in[3];
    const float* W_xprj = (const float*)d_in[4];
    const float* W_dt   = (const float*)d_in[5];
    const float* b_dt   = (const float*)d_in[6];
    const float* A_log  = (const float*)d_in[7];
    const float* Dvec   = (const float*)d_in[8];
    const float* W_out  = (const float*)d_in[9];
    const float* gamma  = (const float*)d_in[10];
    const float* beta   = (const float*)d_in[11];
    float* out = (float*)d_out;

    float *xz, *dbl, *dt, *y;
    cudaGetSymbolAddress((void**)&xz,  g_xz);
    cudaGetSymbolAddress((void**)&dbl, g_dbl);
    cudaGetSymbolAddress((void**)&dt,  g_dt);
    cudaGetSymbolAddress((void**)&y,   g_y);

    // SMEM: 2*(BM*36) + 2*(BK*(BN+8)) floats = 71680 bytes for 128x128
    const int SMG = (2*128*36 + 2*32*136)*4;
    cudaFuncSetAttribute(mma_gemm<128,128,4,2,0>, cudaFuncAttributeMaxDynamicSharedMemorySize, SMG);
    cudaFuncSetAttribute(mma_gemm<128,128,4,2,1>, cudaFuncAttributeMaxDynamicSharedMemorySize, SMG);
    cudaFuncSetAttribute(mma_gemm<128,128,4,2,2>, cudaFuncAttributeMaxDynamicSharedMemorySize, SMG);

    // 0-3) xz = x @ W_in in 4 N-strips of 512 (idx 3 = ncu capture target)
    for (int st = 0; st < 4; st++) {
        mma_gemm<128,128,4,2,0><<<dim3(4, NROWS/128), 256, SMG>>>(
            x, DMODEL, W_in + st*512, 2*DINNER, nullptr, nullptr,
            xz + st*512, 2*DINNER, DMODEL);
    }

    // 4) fused conv+silu+xproj
    xproj_conv_kernel<<<NROWS/64, 128>>>(conv_w, conv_b, W_xprj);

    // 5) dt = softplus(dtr @ W_dt + b_dt)   (K=32)
    mma_gemm<128,128,4,2,2><<<dim3(DINNER/128, NROWS/128), 256, SMG>>>(
        dbl, DBLC, W_dt, DINNER, nullptr, b_dt, dt, DINNER, DTRANK);

    // 6) chunked scan pass 1
    scan_part1<<<(BSZ*NCH*DINNER*DSTATE)/128, 128>>>(A_log);

    // 7) combine + correction + gating
    scan_part3<<<(BSZ*NCH*DINNER*DSTATE)/128, 128>>>(A_log, Dvec);

    // 8) h2 = y @ W_out + x
    mma_gemm<128,128,4,2,1><<<dim3(DMODEL/128, NROWS/128), 256, SMG>>>(
        y, DINNER, W_out, DMODEL, x, nullptr, out, DMODEL, DINNER);

    // 9) LayerNorm
    ln_kernel<<<NROWS, 256>>>(out, gamma, beta);
}

// round 12
// speedup vs baseline: 1.1275x; 1.1275x over previous
#include <cuda_runtime.h>
#include <math.h>
#include <stdint.h>

#define BSZ    2
#define LSEQ   2048
#define DMODEL 512
#define DINNER 1024
#define DSTATE 16
#define DTRANK 32
#define DCONV  4
#define NROWS  (BSZ*LSEQ)          // 4096
#define DBLC   (DTRANK + 2*DSTATE) // 64
#define NCH    8
#define CL     (LSEQ/NCH)          // 256

// ---------------- scratch (device globals; no allocs allowed) ----------------
__device__ float g_xz  [NROWS * 2 * DINNER];
__device__ float g_xc  [NROWS * DINNER];
__device__ float g_dbl [NROWS * DBLC];
__device__ float g_dt  [NROWS * DINNER];
__device__ float g_y   [NROWS * DINNER];
__device__ float g_hend[BSZ*NCH*DINNER*DSTATE];
__device__ float g_pend[BSZ*NCH*DINNER*DSTATE];

__device__ __forceinline__ float f2tf32(float x) {
    uint32_t u;
    asm("cvt.rna.tf32.f32 %0, %1;" : "=r"(u) : "f"(x));
    return __uint_as_float(u);
}

__device__ __forceinline__ void mma_tf32(float c[4], const uint32_t a[4],
                                         const uint32_t b[2]) {
    asm volatile(
        "mma.sync.aligned.m16n8k8.row.col.f32.tf32.tf32.f32 "
        "{%0,%1,%2,%3}, {%4,%5,%6,%7}, {%8,%9}, {%0,%1,%2,%3};"
        : "+f"(c[0]), "+f"(c[1]), "+f"(c[2]), "+f"(c[3])
        : "r"(a[0]), "r"(a[1]), "r"(a[2]), "r"(a[3]), "r"(b[0]), "r"(b[1]));
}

__device__ __forceinline__ void cp_async16(uint32_t dst, const void* src) {
    asm volatile("cp.async.cg.shared.global [%0], [%1], 16;" :: "r"(dst), "l"(src));
}
#define CP_COMMIT() asm volatile("cp.async.commit_group;" ::: "memory")
#define CP_WAIT1()  asm volatile("cp.async.wait_group 1;"  ::: "memory")
#define CP_WAIT0()  asm volatile("cp.async.wait_group 0;"  ::: "memory")

// XOR swizzle used by the fused xproj kernel (unchanged, verified).
template<int LD>
__device__ __forceinline__ int swz(int c, int m) {
    return c*LD + (m ^ ((c & 3) << 3) ^ (((c >> 2) & 7) << 2));
}

__global__ void noop_kernel() {}

// ---------------------------------------------------------------------------
// 3-stage cp.async TF32 warp-MMA GEMM, BK=16.
// C[M,N] = A[M,K](lda) @ W[K,N](ldb), row-major fp32 in gmem; fp32 bits fed
// to tf32 MMA (HW truncation). A staged [m][k] LDA=20; B staged [k][n]
// LDB=BN+8. Both fragment patterns bank-conflict-free (verified).
// MODE 0: C=D. 1: C=D+RES. 2: C=softplus(D+bias).
// ---------------------------------------------------------------------------
template<int BM, int BN, int WARPS_M, int WARPS_N, int MODE>
__global__ void __launch_bounds__(WARPS_M*WARPS_N*32, 2)
mma_gemm(const float* __restrict__ A, int lda,
         const float* __restrict__ W, int ldb,
         const float* __restrict__ RES,
         const float* __restrict__ bias,
         float* __restrict__ C, int N, int K)
{
    constexpr int BK  = 16;
    constexpr int LDA = BK + 4;      // 20
    constexpr int LDB = BN + 8;      // 136
    constexpr int THREADS = WARPS_M*WARPS_N*32;
    constexpr int WM = BM/WARPS_M, WN = BN/WARPS_N;
    constexpr int MT = WM/16, NT = WN/8;
    constexpr int A_CH = (BM*(BK/4)) / THREADS;   // 2 for 128x16/256
    constexpr int B_CH = ((BK*BN)/4) / THREADS;   // 2
    constexpr int STG  = BM*LDA + BK*LDB;         // floats per stage

    extern __shared__ float sm[];

    const int tid  = threadIdx.x;
    const int wid  = tid >> 5;
    const int lane = tid & 31;
    const int g    = lane >> 2;
    const int q    = lane & 3;
    const int wm0  = (wid % WARPS_M) * WM;
    const int wn0  = (wid / WARPS_M) * WN;
    const int bm   = blockIdx.y * BM;
    const int bn   = blockIdx.x * BN;

    const uint32_t smb = (uint32_t)__cvta_generic_to_shared(sm);

    float acc[MT][NT][4];
    #pragma unroll
    for (int i = 0; i < MT; i++)
        #pragma unroll
        for (int j = 0; j < NT; j++)
            #pragma unroll
            for (int v = 0; v < 4; v++) acc[i][j][v] = 0.f;

    const int nK = K / BK;

    auto load_tile = [&](int stage, int kb) {
        uint32_t base = smb + (uint32_t)(stage*STG)*4;
        int k0 = kb*BK;
        #pragma unroll
        for (int i = 0; i < A_CH; i++) {
            int idx = tid + i*THREADS;
            int r = idx >> 2, c4 = idx & 3;
            cp_async16(base + (uint32_t)(r*LDA + c4*4)*4,
                       A + (long)(bm + r)*lda + k0 + c4*4);
        }
        base += (uint32_t)(BM*LDA)*4;
        #pragma unroll
        for (int i = 0; i < B_CH; i++) {
            int idx = tid + i*THREADS;
            int kr = idx / (BN/4), nc4 = idx % (BN/4);
            cp_async16(base + (uint32_t)(kr*LDB + nc4*4)*4,
                       W + (long)(k0 + kr)*ldb + bn + nc4*4);
        }
        CP_COMMIT();
    };

    load_tile(0, 0);
    if (nK > 1) load_tile(1, 1); else CP_COMMIT();  // keep group count consistent

    for (int kb = 0; kb < nK; kb++) {
        CP_WAIT1();            // tile kb resident
        __syncthreads();       // all warps done with buffer (kb-1)%3 -> reusable
        if (kb + 2 < nK) load_tile((kb + 2) % 3, kb + 2);
        else CP_COMMIT();      // keep pending-group arithmetic uniform

        const float* As = sm + (kb % 3)*STG;
        const float* Bs = As + BM*LDA;

        #pragma unroll
        for (int kk = 0; kk < BK/8; kk++) {
            const int kbk = kk*8;
            uint32_t ah[MT][4], bh[NT][2];
            #pragma unroll
            for (int i = 0; i < MT; i++) {
                int m0 = wm0 + i*16 + g;
                ah[i][0] = __float_as_uint(As[(m0    )*LDA + kbk + q    ]);
                ah[i][1] = __float_as_uint(As[(m0 + 8)*LDA + kbk + q    ]);
                ah[i][2] = __float_as_uint(As[(m0    )*LDA + kbk + q + 4]);
                ah[i][3] = __float_as_uint(As[(m0 + 8)*LDA + kbk + q + 4]);
            }
            #pragma unroll
            for (int j = 0; j < NT; j++) {
                int n0 = wn0 + j*8 + g;
                bh[j][0] = __float_as_uint(Bs[(kbk + q    )*LDB + n0]);
                bh[j][1] = __float_as_uint(Bs[(kbk + q + 4)*LDB + n0]);
            }
            #pragma unroll
            for (int i = 0; i < MT; i++)
                #pragma unroll
                for (int j = 0; j < NT; j++)
                    mma_tf32(acc[i][j], ah[i], bh[j]);
        }
        __syncthreads();
    }
    CP_WAIT0();

    // epilogue (mapping identical to verified R5/R8 kernels)
    #pragma unroll
    for (int i = 0; i < MT; i++) {
        #pragma unroll
        for (int half = 0; half < 2; half++) {
            int row = bm + wm0 + i*16 + g + half*8;
            #pragma unroll
            for (int j = 0; j < NT; j++) {
                int col = bn + wn0 + j*8 + 2*q;
                float v0 = acc[i][j][half*2 + 0];
                float v1 = acc[i][j][half*2 + 1];
                long base = (long)row*N + col;
                if (MODE == 1) {
                    v0 += RES[base]; v1 += RES[base + 1];
                } else if (MODE == 2) {
                    v0 += bias[col]; v1 += bias[col + 1];
                    v0 = (v0 > 20.f) ? v0 : log1pf(expf(v0));
                    v1 = (v1 > 20.f) ? v1 : log1pf(expf(v1));
                }
                *(float2*)(C + base) = make_float2(v0, v1);
            }
        }
    }
}

// ---------------------------------------------------------------------------
// Fused conv+silu+xproj (unchanged from passing R8/R9 kernel).
// ---------------------------------------------------------------------------
__global__ void __launch_bounds__(128)
xproj_conv_kernel(const float* __restrict__ conv_w,
                  const float* __restrict__ conv_b,
                  const float* __restrict__ Wx)
{
    constexpr int BM = 64, BN = 64, BK = 32;
    constexpr int MT = 2, NT = 4;

    __shared__ float As[BK*BM];
    __shared__ float Bs[BK*BN];

    const int tid  = threadIdx.x;
    const int wid  = tid >> 5;
    const int lane = tid & 31;
    const int g    = lane >> 2;
    const int q    = lane & 3;
    const int wm0  = (wid & 1) * 32;
    const int wn0  = (wid >> 1) * 32;
    const int bm   = blockIdx.x * BM;

    float acc[MT][NT][4];
    #pragma unroll
    for (int i = 0; i < MT; i++)
        #pragma unroll
        for (int j = 0; j < NT; j++)
            #pragma unroll
            for (int v = 0; v < 4; v++) acc[i][j][v] = 0.f;

    for (int k0 = 0; k0 < DINNER; k0 += BK) {
        #pragma unroll
        for (int i = 0; i < 4; i++) {
            int idx = tid + i*128;
            int r = idx >> 3, c4 = idx & 7;
            int m = bm + r;
            int l = m & (LSEQ - 1);
            int k = k0 + c4*4;

            float tv[4][4];
            #pragma unroll
            for (int j = 0; j < 4; j++) {
                float4 t = make_float4(0.f, 0.f, 0.f, 0.f);
                if (l - 3 + j >= 0)
                    t = *(const float4*)(g_xz + (long)(m - 3 + j)*(2*DINNER) + k);
                tv[j][0] = t.x; tv[j][1] = t.y; tv[j][2] = t.z; tv[j][3] = t.w;
            }
            float4 cb = *(const float4*)(conv_b + k);
            float cbv[4] = {cb.x, cb.y, cb.z, cb.w};
            float xo[4];
            #pragma unroll
            for (int cc = 0; cc < 4; cc++) {
                float4 w = *(const float4*)(conv_w + (k + cc)*DCONV);
                float a = cbv[cc] + w.x*tv[0][cc] + w.y*tv[1][cc]
                                  + w.z*tv[2][cc] + w.w*tv[3][cc];
                float sig = 1.f / (1.f + __expf(-a));
                xo[cc] = a * sig;
                As[swz<BM>(c4*4 + cc, r)] = f2tf32(xo[cc]);
            }
            *(float4*)(g_xc + (long)m*DINNER + k) =
                make_float4(xo[0], xo[1], xo[2], xo[3]);
        }
        #pragma unroll
        for (int i = 0; i < 4; i++) {
            int idx = tid + i*128;
            int kr = idx >> 4, nc4 = idx & 15;
            float4 v = *(const float4*)(Wx + (long)(k0 + kr)*DBLC + nc4*4);
            float4 t;
            t.x = f2tf32(v.x); t.y = f2tf32(v.y);
            t.z = f2tf32(v.z); t.w = f2tf32(v.w);
            *(float4*)(Bs + swz<BN>(kr, nc4*4)) = t;
        }
        __syncthreads();

        #pragma unroll
        for (int kk = 0; kk < 4; kk++) {
            const int kb = kk*8;
            uint32_t ah[MT][4], bh[NT][2];
            #pragma unroll
            for (int i = 0; i < MT; i++) {
                int m0 = wm0 + i*16 + g;
                ah[i][0] = __float_as_uint(As[swz<BM>(kb+q,   m0    )]);
                ah[i][1] = __float_as_uint(As[swz<BM>(kb+q,   m0 + 8)]);
                ah[i][2] = __float_as_uint(As[swz<BM>(kb+q+4, m0    )]);
                ah[i][3] = __float_as_uint(As[swz<BM>(kb+q+4, m0 + 8)]);
            }
            #pragma unroll
            for (int j = 0; j < NT; j++) {
                int n0 = wn0 + j*8 + g;
                bh[j][0] = __float_as_uint(Bs[swz<BN>(kb+q,   n0)]);
                bh[j][1] = __float_as_uint(Bs[swz<BN>(kb+q+4, n0)]);
            }
            #pragma unroll
            for (int i = 0; i < MT; i++)
                #pragma unroll
                for (int j = 0; j < NT; j++)
                    mma_tf32(acc[i][j], ah[i], bh[j]);
        }
        __syncthreads();
    }

    #pragma unroll
    for (int i = 0; i < MT; i++) {
        #pragma unroll
        for (int half = 0; half < 2; half++) {
            int row = bm + wm0 + i*16 + g + half*8;
            #pragma unroll
            for (int j = 0; j < NT; j++) {
                int col = wn0 + j*8 + 2*q;
                *(float2*)(g_dbl + (long)row*DBLC + col) =
                    make_float2(acc[i][j][half*2 + 0], acc[i][j][half*2 + 1]);
            }
        }
    }
}

// ---------------------------------------------------------------------------
// Chunked scan pass 1. Pointer-based addressing, unroll 8.
// gid -> s=gid&15, d=(gid>>4)&1023, ch=(gid>>14)&7, b=gid>>17.
// ---------------------------------------------------------------------------
__global__ void __launch_bounds__(128) scan_part1(const float* __restrict__ A_log)
{
    int gid = blockIdx.x * 128 + threadIdx.x;
    int s  = gid & 15;
    int d  = (gid >> 4) & 1023;
    int ch = (gid >> 14) & 7;
    int b  = gid >> 17;

    const float A = -expf(A_log[d*DSTATE + s]);
    float h = 0.f, P = 1.f;

    long r0 = (long)(b*LSEQ + ch*CL);
    const float* pdt = g_dt  + r0*DINNER + d;
    const float* pxc = g_xc  + r0*DINNER + d;
    const float* pB  = g_dbl + r0*DBLC + DTRANK + s;
    const float* pC  = pB + DSTATE;
    float*       py  = g_y   + r0*DINNER + d;

    for (int t0 = 0; t0 < CL; t0 += 8) {
        float dtv[8], xv[8], Bv[8], Cv[8];
        #pragma unroll
        for (int u = 0; u < 8; u++) {
            dtv[u] = pdt[u*DINNER];
            xv [u] = pxc[u*DINNER];
            Bv [u] = pB [u*DBLC];
            Cv [u] = pC [u*DBLC];
        }
        float p[8];
        #pragma unroll
        for (int u = 0; u < 8; u++) {
            float dA = __expf(dtv[u] * A);
            h = h * dA + (dtv[u] * xv[u]) * Bv[u];
            P *= dA;
            p[u] = h * Cv[u];
        }
        #pragma unroll
        for (int off = 8; off; off >>= 1) {
            #pragma unroll
            for (int u = 0; u < 8; u++)
                p[u] += __shfl_xor_sync(0xffffffffu, p[u], off);
        }
        if (s == 0) {
            #pragma unroll
            for (int u = 0; u < 8; u++) py[u*DINNER] = p[u];
        }
        pdt += 8*DINNER; pxc += 8*DINNER; pB += 8*DBLC; pC += 8*DBLC; py += 8*DINNER;
    }
    long idx = ((long)((b*NCH + ch)*DINNER + d))*DSTATE + s;
    g_hend[idx] = h;
    g_pend[idx] = P;
}

// Pass 2: chain predecessors, add correction, apply D-skip + silu(z) gating.
__global__ void __launch_bounds__(128) scan_part3(const float* __restrict__ A_log,
                                                  const float* __restrict__ Dvec)
{
    int gid = blockIdx.x * 128 + threadIdx.x;
    int s  = gid & 15;
    int d  = (gid >> 4) & 1023;
    int ch = (gid >> 14) & 7;
    int b  = gid >> 17;

    const float A  = -expf(A_log[d*DSTATE + s]);
    const float Dv = Dvec[d];

    float hin = 0.f;
    for (int c = 0; c < ch; c++) {
        long idx = ((long)((b*NCH + c)*DINNER + d))*DSTATE + s;
        hin = g_pend[idx] * hin + g_hend[idx];
    }

    long r0 = (long)(b*LSEQ + ch*CL);
    const float* pdt = g_dt  + r0*DINNER + d;
    const float* pxc = g_xc  + r0*DINNER + d;
    const float* pC  = g_dbl + r0*DBLC + DTRANK + DSTATE + s;
    const float* pz  = g_xz  + r0*(2*DINNER) + DINNER + d;
    float*       py  = g_y   + r0*DINNER + d;

    float P = 1.f;
    for (int t0 = 0; t0 < CL; t0 += 8) {
        float dtv[8], Cv[8];
        #pragma unroll
        for (int u = 0; u < 8; u++) {
            dtv[u] = pdt[u*DINNER];
            Cv [u] = pC [u*DBLC];
        }
        float p[8];
        #pragma unroll
        for (int u = 0; u < 8; u++) {
            P *= __expf(dtv[u] * A);
            p[u] = (P * hin) * Cv[u];
        }
        #pragma unroll
        for (int off = 8; off; off >>= 1) {
            #pragma unroll
            for (int u = 0; u < 8; u++)
                p[u] += __shfl_xor_sync(0xffffffffu, p[u], off);
        }
        if (s == 0) {
            #pragma unroll
            for (int u = 0; u < 8; u++) {
                float y  = py[u*DINNER] + p[u];
                float xv = pxc[u*DINNER];
                float zv = pz [u*2*DINNER];
                float sig = 1.f / (1.f + __expf(-zv));
                py[u*DINNER] = (y + xv*Dv) * (zv * sig);
            }
        }
        pdt += 8*DINNER; pxc += 8*DINNER; pC += 8*DBLC;
        pz  += 8*2*DINNER; py += 8*DINNER;
    }
}

// ---------------------------------------------------------------------------
// LayerNorm over rows of 512 (in-place)
// ---------------------------------------------------------------------------
__global__ void ln_kernel(float* __restrict__ out,
                          const float* __restrict__ gamma,
                          const float* __restrict__ beta)
{
    int row = blockIdx.x;
    int t   = threadIdx.x;
    float v0 = out[(long)row*DMODEL + t];
    float v1 = out[(long)row*DMODEL + 256 + t];

    float s = v0 + v1;
    float qq = v0*v0 + v1*v1;
    #pragma unroll
    for (int o = 16; o; o >>= 1) {
        s  += __shfl_xor_sync(0xffffffffu, s, o);
        qq += __shfl_xor_sync(0xffffffffu, qq, o);
    }
    __shared__ float s1[8], s2[8];
    int wid = t >> 5, lane = t & 31;
    if (lane == 0) { s1[wid] = s; s2[wid] = qq; }
    __syncthreads();
    if (t == 0) {
        float ts = 0.f, tq = 0.f;
        #pragma unroll
        for (int i = 0; i < 8; i++) { ts += s1[i]; tq += s2[i]; }
        float mu = ts / DMODEL;
        s1[0] = mu;
        s2[0] = tq / DMODEL - mu*mu;
    }
    __syncthreads();
    float mu  = s1[0];
    float inv = rsqrtf(s2[0] + 1e-5f);
    out[(long)row*DMODEL + t]       = (v0 - mu) * inv * gamma[t]       + beta[t];
    out[(long)row*DMODEL + 256 + t] = (v1 - mu) * inv * gamma[256 + t] + beta[256 + t];
}

// ---------------------------------------------------------------------------
extern "C" void kernel_launch(void* const* d_in, const int* in_sizes, int n_in,
                              void* d_out, int out_size)
{
    const float* x      = (const float*)d_in[0];
    const float* W_in   = (const float*)d_in[1];
    const float* conv_w = (const float*)d_in[2];
    const float* conv_b = (const float*)d_in[3];
    const float* W_xprj = (const float*)d_in[4];
    const float* W_dt   = (const float*)d_in[5];
    const float* b_dt   = (const float*)d_in[6];
    const float* A_log  = (const float*)d_in[7];
    const float* Dvec   = (const float*)d_in[8];
    const float* W_out  = (const float*)d_in[9];
    const float* gamma  = (const float*)d_in[10];
    const float* beta   = (const float*)d_in[11];
    float* out = (float*)d_out;

    float *xz, *dbl, *dt, *y;
    cudaGetSymbolAddress((void**)&xz,  g_xz);
    cudaGetSymbolAddress((void**)&dbl, g_dbl);
    cudaGetSymbolAddress((void**)&dt,  g_dt);
    cudaGetSymbolAddress((void**)&y,   g_y);

    // 3 stages x (128*20 + 16*136) floats = 56832 bytes
    const int SMG = 3*(128*20 + 16*136)*4;
    cudaFuncSetAttribute(mma_gemm<128,128,4,2,0>, cudaFuncAttributeMaxDynamicSharedMemorySize, SMG);
    cudaFuncSetAttribute(mma_gemm<128,128,4,2,1>, cudaFuncAttributeMaxDynamicSharedMemorySize, SMG);
    cudaFuncSetAttribute(mma_gemm<128,128,4,2,2>, cudaFuncAttributeMaxDynamicSharedMemorySize, SMG);
    cudaFuncSetAttribute(mma_gemm<128,128,4,2,0>, cudaFuncAttributePreferredSharedMemoryCarveout, 100);
    cudaFuncSetAttribute(mma_gemm<128,128,4,2,1>, cudaFuncAttributePreferredSharedMemoryCarveout, 100);
    cudaFuncSetAttribute(mma_gemm<128,128,4,2,2>, cudaFuncAttributePreferredSharedMemoryCarveout, 100);

    // 0-2) no-ops so launch index 3 (ncu capture) = the new pipelined GEMM
    noop_kernel<<<1, 32>>>();
    noop_kernel<<<1, 32>>>();
    noop_kernel<<<1, 32>>>();

    // 3) xz = x @ W_in   (4096 x 2048, K=512) — single launch, grid 512
    mma_gemm<128,128,4,2,0><<<dim3(2*DINNER/128, NROWS/128), 256, SMG>>>(
        x, DMODEL, W_in, 2*DINNER, nullptr, nullptr, xz, 2*DINNER, DMODEL);

    // 4) fused conv+silu+xproj
    xproj_conv_kernel<<<NROWS/64, 128>>>(conv_w, conv_b, W_xprj);

    // 5) dt = softplus(dtr @ W_dt + b_dt)   (K=32)
    mma_gemm<128,128,4,2,2><<<dim3(DINNER/128, NROWS/128), 256, SMG>>>(
        dbl, DBLC, W_dt, DINNER, nullptr, b_dt, dt, DINNER, DTRANK);

    // 6) chunked scan pass 1
    scan_part1<<<(BSZ*NCH*DINNER*DSTATE)/128, 128>>>(A_log);

    // 7) combine + correction + gating
    scan_part3<<<(BSZ*NCH*DINNER*DSTATE)/128, 128>>>(A_log, Dvec);

    // 8) h2 = y @ W_out + x
    mma_gemm<128,128,4,2,1><<<dim3(DMODEL/128, NROWS/128), 256, SMG>>>(
        y, DINNER, W_out, DMODEL, x, nullptr, out, DMODEL, DINNER);

    // 9) LayerNorm
    ln_kernel<<<NROWS, 256>>>(out, gamma, beta);
}

// round 14
// speedup vs baseline: 1.3241x; 1.1744x over previous
#include <cuda_runtime.h>
#include <math.h>
#include <stdint.h>

#define BSZ    2
#define LSEQ   2048
#define DMODEL 512
#define DINNER 1024
#define DSTATE 16
#define DTRANK 32
#define DCONV  4
#define NROWS  (BSZ*LSEQ)          // 4096
#define DBLC   (DTRANK + 2*DSTATE) // 64
#define NCH    8
#define CL     (LSEQ/NCH)          // 256

// ---------------- scratch (device globals; no allocs allowed) ----------------
__device__ float g_xz  [NROWS * 2 * DINNER];
__device__ float g_xc  [NROWS * DINNER];
__device__ float g_dbl [NROWS * DBLC];
__device__ float g_dt  [NROWS * DINNER];
__device__ float g_y   [NROWS * DINNER];
__device__ float g_hend[BSZ*NCH*DINNER*DSTATE];
__device__ float g_pend[BSZ*NCH*DINNER*DSTATE];

__device__ __forceinline__ float f2tf32(float x) {
    uint32_t u;
    asm("cvt.rna.tf32.f32 %0, %1;" : "=r"(u) : "f"(x));
    return __uint_as_float(u);
}

__device__ __forceinline__ void mma_tf32(float c[4], const uint32_t a[4],
                                         const uint32_t b[2]) {
    asm volatile(
        "mma.sync.aligned.m16n8k8.row.col.f32.tf32.tf32.f32 "
        "{%0,%1,%2,%3}, {%4,%5,%6,%7}, {%8,%9}, {%0,%1,%2,%3};"
        : "+f"(c[0]), "+f"(c[1]), "+f"(c[2]), "+f"(c[3])
        : "r"(a[0]), "r"(a[1]), "r"(a[2]), "r"(a[3]), "r"(b[0]), "r"(b[1]));
}

__device__ __forceinline__ void cp_async16(uint32_t dst, const void* src) {
    asm volatile("cp.async.cg.shared.global [%0], [%1], 16;" :: "r"(dst), "l"(src));
}
#define CP_COMMIT() asm volatile("cp.async.commit_group;" ::: "memory")
#define CP_WAIT1()  asm volatile("cp.async.wait_group 1;"  ::: "memory")
#define CP_WAIT0()  asm volatile("cp.async.wait_group 0;"  ::: "memory")

// XOR swizzle used by the fused xproj kernel (unchanged, verified).
template<int LD>
__device__ __forceinline__ int swz(int c, int m) {
    return c*LD + (m ^ ((c & 3) << 3) ^ (((c >> 2) & 7) << 2));
}

// ---------------------------------------------------------------------------
// 3-stage cp.async TF32 warp-MMA GEMM, BK=32.
// A staged [m][k] LDA=36 (fragment banks 4g+q distinct); B staged [k][n]
// LDB=BN+8 (banks 8q+g distinct). fp32 bits -> tf32 MMA (HW truncation).
// MODE 0: C=D. 1: C=D+RES. 2: C=softplus(D+bias).
// ---------------------------------------------------------------------------
template<int BM, int BN, int WARPS_M, int WARPS_N, int MODE>
__global__ void __launch_bounds__(WARPS_M*WARPS_N*32, 2)
mma_gemm(const float* __restrict__ A, int lda,
         const float* __restrict__ W, int ldb,
         const float* __restrict__ RES,
         const float* __restrict__ bias,
         float* __restrict__ C, int N, int K)
{
    constexpr int BK  = 32;
    constexpr int LDA = BK + 4;      // 36
    constexpr int LDB = BN + 8;      // 136
    constexpr int THREADS = WARPS_M*WARPS_N*32;
    constexpr int WM = BM/WARPS_M, WN = BN/WARPS_N;
    constexpr int MT = WM/16, NT = WN/8;
    constexpr int A_CH = (BM*(BK/4)) / THREADS;   // 4
    constexpr int B_CH = ((BK*BN)/4) / THREADS;   // 4
    constexpr int STG  = BM*LDA + BK*LDB;

    extern __shared__ float sm[];

    const int tid  = threadIdx.x;
    const int wid  = tid >> 5;
    const int lane = tid & 31;
    const int g    = lane >> 2;
    const int q    = lane & 3;
    const int wm0  = (wid % WARPS_M) * WM;
    const int wn0  = (wid / WARPS_M) * WN;
    const int bm   = blockIdx.y * BM;
    const int bn   = blockIdx.x * BN;

    const uint32_t smb = (uint32_t)__cvta_generic_to_shared(sm);

    float acc[MT][NT][4];
    #pragma unroll
    for (int i = 0; i < MT; i++)
        #pragma unroll
        for (int j = 0; j < NT; j++)
            #pragma unroll
            for (int v = 0; v < 4; v++) acc[i][j][v] = 0.f;

    const int nK = K / BK;

    auto load_tile = [&](int stage, int kb) {
        uint32_t base = smb + (uint32_t)(stage*STG)*4;
        int k0 = kb*BK;
        #pragma unroll
        for (int i = 0; i < A_CH; i++) {
            int idx = tid + i*THREADS;
            int r = idx >> 3, c4 = idx & 7;
            cp_async16(base + (uint32_t)(r*LDA + c4*4)*4,
                       A + (long)(bm + r)*lda + k0 + c4*4);
        }
        base += (uint32_t)(BM*LDA)*4;
        #pragma unroll
        for (int i = 0; i < B_CH; i++) {
            int idx = tid + i*THREADS;
            int kr = idx / (BN/4), nc4 = idx % (BN/4);
            cp_async16(base + (uint32_t)(kr*LDB + nc4*4)*4,
                       W + (long)(k0 + kr)*ldb + bn + nc4*4);
        }
        CP_COMMIT();
    };

    load_tile(0, 0);
    if (nK > 1) load_tile(1, 1); else CP_COMMIT();

    for (int kb = 0; kb < nK; kb++) {
        CP_WAIT1();
        __syncthreads();
        if (kb + 2 < nK) load_tile((kb + 2) % 3, kb + 2);
        else CP_COMMIT();

        const float* As = sm + (kb % 3)*STG;
        const float* Bs = As + BM*LDA;

        #pragma unroll
        for (int kk = 0; kk < BK/8; kk++) {
            const int kbk = kk*8;
            uint32_t ah[MT][4], bh[NT][2];
            #pragma unroll
            for (int i = 0; i < MT; i++) {
                int m0 = wm0 + i*16 + g;
                ah[i][0] = __float_as_uint(As[(m0    )*LDA + kbk + q    ]);
                ah[i][1] = __float_as_uint(As[(m0 + 8)*LDA + kbk + q    ]);
                ah[i][2] = __float_as_uint(As[(m0    )*LDA + kbk + q + 4]);
                ah[i][3] = __float_as_uint(As[(m0 + 8)*LDA + kbk + q + 4]);
            }
            #pragma unroll
            for (int j = 0; j < NT; j++) {
                int n0 = wn0 + j*8 + g;
                bh[j][0] = __float_as_uint(Bs[(kbk + q    )*LDB + n0]);
                bh[j][1] = __float_as_uint(Bs[(kbk + q + 4)*LDB + n0]);
            }
            #pragma unroll
            for (int i = 0; i < MT; i++)
                #pragma unroll
                for (int j = 0; j < NT; j++)
                    mma_tf32(acc[i][j], ah[i], bh[j]);
        }
        __syncthreads();
    }
    CP_WAIT0();

    #pragma unroll
    for (int i = 0; i < MT; i++) {
        #pragma unroll
        for (int half = 0; half < 2; half++) {
            int row = bm + wm0 + i*16 + g + half*8;
            #pragma unroll
            for (int j = 0; j < NT; j++) {
                int col = bn + wn0 + j*8 + 2*q;
                float v0 = acc[i][j][half*2 + 0];
                float v1 = acc[i][j][half*2 + 1];
                long base = (long)row*N + col;
                if (MODE == 1) {
                    v0 += RES[base]; v1 += RES[base + 1];
                } else if (MODE == 2) {
                    v0 += bias[col]; v1 += bias[col + 1];
                    v0 = (v0 > 20.f) ? v0 : log1pf(expf(v0));
                    v1 = (v1 > 20.f) ? v1 : log1pf(expf(v1));
                }
                *(float2*)(C + base) = make_float2(v0, v1);
            }
        }
    }
}

// ---------------------------------------------------------------------------
// Fused conv+silu+xproj (unchanged, verified).
// ---------------------------------------------------------------------------
__global__ void __launch_bounds__(128)
xproj_conv_kernel(const float* __restrict__ conv_w,
                  const float* __restrict__ conv_b,
                  const float* __restrict__ Wx)
{
    constexpr int BM = 64, BN = 64, BK = 32;
    constexpr int MT = 2, NT = 4;

    __shared__ float As[BK*BM];
    __shared__ float Bs[BK*BN];

    const int tid  = threadIdx.x;
    const int wid  = tid >> 5;
    const int lane = tid & 31;
    const int g    = lane >> 2;
    const int q    = lane & 3;
    const int wm0  = (wid & 1) * 32;
    const int wn0  = (wid >> 1) * 32;
    const int bm   = blockIdx.x * BM;

    float acc[MT][NT][4];
    #pragma unroll
    for (int i = 0; i < MT; i++)
        #pragma unroll
        for (int j = 0; j < NT; j++)
            #pragma unroll
            for (int v = 0; v < 4; v++) acc[i][j][v] = 0.f;

    for (int k0 = 0; k0 < DINNER; k0 += BK) {
        #pragma unroll
        for (int i = 0; i < 4; i++) {
            int idx = tid + i*128;
            int r = idx >> 3, c4 = idx & 7;
            int m = bm + r;
            int l = m & (LSEQ - 1);
            int k = k0 + c4*4;

            float tv[4][4];
            #pragma unroll
            for (int j = 0; j < 4; j++) {
                float4 t = make_float4(0.f, 0.f, 0.f, 0.f);
                if (l - 3 + j >= 0)
                    t = *(const float4*)(g_xz + (long)(m - 3 + j)*(2*DINNER) + k);
                tv[j][0] = t.x; tv[j][1] = t.y; tv[j][2] = t.z; tv[j][3] = t.w;
            }
            float4 cb = *(const float4*)(conv_b + k);
            float cbv[4] = {cb.x, cb.y, cb.z, cb.w};
            float xo[4];
            #pragma unroll
            for (int cc = 0; cc < 4; cc++) {
                float4 w = *(const float4*)(conv_w + (k + cc)*DCONV);
                float a = cbv[cc] + w.x*tv[0][cc] + w.y*tv[1][cc]
                                  + w.z*tv[2][cc] + w.w*tv[3][cc];
                float sig = 1.f / (1.f + __expf(-a));
                xo[cc] = a * sig;
                As[swz<BM>(c4*4 + cc, r)] = f2tf32(xo[cc]);
            }
            *(float4*)(g_xc + (long)m*DINNER + k) =
                make_float4(xo[0], xo[1], xo[2], xo[3]);
        }
        #pragma unroll
        for (int i = 0; i < 4; i++) {
            int idx = tid + i*128;
            int kr = idx >> 4, nc4 = idx & 15;
            float4 v = *(const float4*)(Wx + (long)(k0 + kr)*DBLC + nc4*4);
            float4 t;
            t.x = f2tf32(v.x); t.y = f2tf32(v.y);
            t.z = f2tf32(v.z); t.w = f2tf32(v.w);
            *(float4*)(Bs + swz<BN>(kr, nc4*4)) = t;
        }
        __syncthreads();

        #pragma unroll
        for (int kk = 0; kk < 4; kk++) {
            const int kb = kk*8;
            uint32_t ah[MT][4], bh[NT][2];
            #pragma unroll
            for (int i = 0; i < MT; i++) {
                int m0 = wm0 + i*16 + g;
                ah[i][0] = __float_as_uint(As[swz<BM>(kb+q,   m0    )]);
                ah[i][1] = __float_as_uint(As[swz<BM>(kb+q,   m0 + 8)]);
                ah[i][2] = __float_as_uint(As[swz<BM>(kb+q+4, m0    )]);
                ah[i][3] = __float_as_uint(As[swz<BM>(kb+q+4, m0 + 8)]);
            }
            #pragma unroll
            for (int j = 0; j < NT; j++) {
                int n0 = wn0 + j*8 + g;
                bh[j][0] = __float_as_uint(Bs[swz<BN>(kb+q,   n0)]);
                bh[j][1] = __float_as_uint(Bs[swz<BN>(kb+q+4, n0)]);
            }
            #pragma unroll
            for (int i = 0; i < MT; i++)
                #pragma unroll
                for (int j = 0; j < NT; j++)
                    mma_tf32(acc[i][j], ah[i], bh[j]);
        }
        __syncthreads();
    }

    #pragma unroll
    for (int i = 0; i < MT; i++) {
        #pragma unroll
        for (int half = 0; half < 2; half++) {
            int row = bm + wm0 + i*16 + g + half*8;
            #pragma unroll
            for (int j = 0; j < NT; j++) {
                int col = wn0 + j*8 + 2*q;
                *(float2*)(g_dbl + (long)row*DBLC + col) =
                    make_float2(acc[i][j][half*2 + 0], acc[i][j][half*2 + 1]);
            }
        }
    }
}

// ---------------------------------------------------------------------------
// Chunked scan, 4 states per thread (2-level shuffle reduce).
// gid -> j=gid&3 (states 4j..4j+3), d=(gid>>2)&1023, ch=(gid>>12)&7, b=gid>>15.
// ---------------------------------------------------------------------------
__global__ void __launch_bounds__(128) scan_part1(const float* __restrict__ A_log)
{
    int gid = blockIdx.x * 128 + threadIdx.x;
    int j  = gid & 3;
    int d  = (gid >> 2) & 1023;
    int ch = (gid >> 12) & 7;
    int b  = gid >> 15;
    int s0 = 4*j;

    float Aa[4], h[4], P[4];
    #pragma unroll
    for (int i = 0; i < 4; i++) {
        Aa[i] = -expf(A_log[d*DSTATE + s0 + i]);
        h[i] = 0.f; P[i] = 1.f;
    }

    long r0 = (long)(b*LSEQ + ch*CL);
    const float* pdt = g_dt  + r0*DINNER + d;
    const float* pxc = g_xc  + r0*DINNER + d;
    const float* pB  = g_dbl + r0*DBLC + DTRANK + s0;
    const float* pC  = pB + DSTATE;
    float*       py  = g_y   + r0*DINNER + d;

    for (int t0 = 0; t0 < CL; t0 += 4) {
        float dtv[4], xv[4];
        float4 Bv[4], Cv[4];
        #pragma unroll
        for (int u = 0; u < 4; u++) {
            dtv[u] = pdt[u*DINNER];
            xv [u] = pxc[u*DINNER];
            Bv [u] = *(const float4*)(pB + u*DBLC);
            Cv [u] = *(const float4*)(pC + u*DBLC);
        }
        float p[4];
        #pragma unroll
        for (int u = 0; u < 4; u++) {
            float q = dtv[u] * xv[u];
            float dA0 = __expf(dtv[u]*Aa[0]);
            float dA1 = __expf(dtv[u]*Aa[1]);
            float dA2 = __expf(dtv[u]*Aa[2]);
            float dA3 = __expf(dtv[u]*Aa[3]);
            h[0] = h[0]*dA0 + q*Bv[u].x;  P[0] *= dA0;
            h[1] = h[1]*dA1 + q*Bv[u].y;  P[1] *= dA1;
            h[2] = h[2]*dA2 + q*Bv[u].z;  P[2] *= dA2;
            h[3] = h[3]*dA3 + q*Bv[u].w;  P[3] *= dA3;
            p[u] = h[0]*Cv[u].x + h[1]*Cv[u].y + h[2]*Cv[u].z + h[3]*Cv[u].w;
        }
        #pragma unroll
        for (int u = 0; u < 4; u++) {
            p[u] += __shfl_xor_sync(0xffffffffu, p[u], 2);
            p[u] += __shfl_xor_sync(0xffffffffu, p[u], 1);
        }
        if (j == 0) {
            #pragma unroll
            for (int u = 0; u < 4; u++) py[u*DINNER] = p[u];
        }
        pdt += 4*DINNER; pxc += 4*DINNER; pB += 4*DBLC; pC += 4*DBLC; py += 4*DINNER;
    }
    long idx = ((long)((b*NCH + ch)*DINNER + d))*DSTATE + s0;
    *(float4*)(g_hend + idx) = make_float4(h[0], h[1], h[2], h[3]);
    *(float4*)(g_pend + idx) = make_float4(P[0], P[1], P[2], P[3]);
}

__global__ void __launch_bounds__(128) scan_part3(const float* __restrict__ A_log,
                                                  const float* __restrict__ Dvec)
{
    int gid = blockIdx.x * 128 + threadIdx.x;
    int j  = gid & 3;
    int d  = (gid >> 2) & 1023;
    int ch = (gid >> 12) & 7;
    int b  = gid >> 15;
    int s0 = 4*j;

    float Aa[4];
    #pragma unroll
    for (int i = 0; i < 4; i++)
        Aa[i] = -expf(A_log[d*DSTATE + s0 + i]);
    const float Dv = Dvec[d];

    float hin[4] = {0.f, 0.f, 0.f, 0.f};
    for (int c = 0; c < ch; c++) {
        long idx = ((long)((b*NCH + c)*DINNER + d))*DSTATE + s0;
        float4 pe = *(const float4*)(g_pend + idx);
        float4 he = *(const float4*)(g_hend + idx);
        hin[0] = pe.x*hin[0] + he.x;
        hin[1] = pe.y*hin[1] + he.y;
        hin[2] = pe.z*hin[2] + he.z;
        hin[3] = pe.w*hin[3] + he.w;
    }

    long r0 = (long)(b*LSEQ + ch*CL);
    const float* pdt = g_dt  + r0*DINNER + d;
    const float* pxc = g_xc  + r0*DINNER + d;
    const float* pC  = g_dbl + r0*DBLC + DTRANK + DSTATE + s0;
    const float* pz  = g_xz  + r0*(2*DINNER) + DINNER + d;
    float*       py  = g_y   + r0*DINNER + d;

    float P[4] = {1.f, 1.f, 1.f, 1.f};
    for (int t0 = 0; t0 < CL; t0 += 4) {
        float dtv[4];
        float4 Cv[4];
        #pragma unroll
        for (int u = 0; u < 4; u++) {
            dtv[u] = pdt[u*DINNER];
            Cv [u] = *(const float4*)(pC + u*DBLC);
        }
        float p[4];
        #pragma unroll
        for (int u = 0; u < 4; u++) {
            P[0] *= __expf(dtv[u]*Aa[0]);
            P[1] *= __expf(dtv[u]*Aa[1]);
            P[2] *= __expf(dtv[u]*Aa[2]);
            P[3] *= __expf(dtv[u]*Aa[3]);
            p[u] = (P[0]*hin[0])*Cv[u].x + (P[1]*hin[1])*Cv[u].y
                 + (P[2]*hin[2])*Cv[u].z + (P[3]*hin[3])*Cv[u].w;
        }
        #pragma unroll
        for (int u = 0; u < 4; u++) {
            p[u] += __shfl_xor_sync(0xffffffffu, p[u], 2);
            p[u] += __shfl_xor_sync(0xffffffffu, p[u], 1);
        }
        if (j == 0) {
            #pragma unroll
            for (int u = 0; u < 4; u++) {
                float y  = py[u*DINNER] + p[u];
                float xv = pxc[u*DINNER];
                float zv = pz [u*2*DINNER];
                float sig = 1.f / (1.f + __expf(-zv));
                py[u*DINNER] = (y + xv*Dv) * (zv * sig);
            }
        }
        pdt += 4*DINNER; pxc += 4*DINNER; pC += 4*DBLC;
        pz  += 4*2*DINNER; py += 4*DINNER;
    }
}

// ---------------------------------------------------------------------------
// LayerNorm over rows of 512 (in-place)
// ---------------------------------------------------------------------------
__global__ void ln_kernel(float* __restrict__ out,
                          const float* __restrict__ gamma,
                          const float* __restrict__ beta)
{
    int row = blockIdx.x;
    int t   = threadIdx.x;
    float v0 = out[(long)row*DMODEL + t];
    float v1 = out[(long)row*DMODEL + 256 + t];

    float s = v0 + v1;
    float qq = v0*v0 + v1*v1;
    #pragma unroll
    for (int o = 16; o; o >>= 1) {
        s  += __shfl_xor_sync(0xffffffffu, s, o);
        qq += __shfl_xor_sync(0xffffffffu, qq, o);
    }
    __shared__ float s1[8], s2[8];
    int wid = t >> 5, lane = t & 31;
    if (lane == 0) { s1[wid] = s; s2[wid] = qq; }
    __syncthreads();
    if (t == 0) {
        float ts = 0.f, tq = 0.f;
        #pragma unroll
        for (int i = 0; i < 8; i++) { ts += s1[i]; tq += s2[i]; }
        float mu = ts / DMODEL;
        s1[0] = mu;
        s2[0] = tq / DMODEL - mu*mu;
    }
    __syncthreads();
    float mu  = s1[0];
    float inv = rsqrtf(s2[0] + 1e-5f);
    out[(long)row*DMODEL + t]       = (v0 - mu) * inv * gamma[t]       + beta[t];
    out[(long)row*DMODEL + 256 + t] = (v1 - mu) * inv * gamma[256 + t] + beta[256 + t];
}

// ---------------------------------------------------------------------------
extern "C" void kernel_launch(void* const* d_in, const int* in_sizes, int n_in,
                              void* d_out, int out_size)
{
    const float* x      = (const float*)d_in[0];
    const float* W_in   = (const float*)d_in[1];
    const float* conv_w = (const float*)d_in[2];
    const float* conv_b = (const float*)d_in[3];
    const float* W_xprj = (const float*)d_in[4];
    const float* W_dt   = (const float*)d_in[5];
    const float* b_dt   = (const float*)d_in[6];
    const float* A_log  = (const float*)d_in[7];
    const float* Dvec   = (const float*)d_in[8];
    const float* W_out  = (const float*)d_in[9];
    const float* gamma  = (const float*)d_in[10];
    const float* beta   = (const float*)d_in[11];
    float* out = (float*)d_out;

    float *xz, *dbl, *dt, *y;
    cudaGetSymbolAddress((void**)&xz,  g_xz);
    cudaGetSymbolAddress((void**)&dbl, g_dbl);
    cudaGetSymbolAddress((void**)&dt,  g_dt);
    cudaGetSymbolAddress((void**)&y,   g_y);

    // 3 stages x (128*36 + 32*136) floats = 107520 bytes
    const int SMG = 3*(128*36 + 32*136)*4;
    cudaFuncSetAttribute(mma_gemm<128,128,4,2,0>, cudaFuncAttributeMaxDynamicSharedMemorySize, SMG);
    cudaFuncSetAttribute(mma_gemm<128,128,4,2,1>, cudaFuncAttributeMaxDynamicSharedMemorySize, SMG);
    cudaFuncSetAttribute(mma_gemm<128,128,4,2,2>, cudaFuncAttributeMaxDynamicSharedMemorySize, SMG);
    cudaFuncSetAttribute(mma_gemm<128,128,4,2,0>, cudaFuncAttributePreferredSharedMemoryCarveout, 100);
    cudaFuncSetAttribute(mma_gemm<128,128,4,2,1>, cudaFuncAttributePreferredSharedMemoryCarveout, 100);
    cudaFuncSetAttribute(mma_gemm<128,128,4,2,2>, cudaFuncAttributePreferredSharedMemoryCarveout, 100);

    // 0) xz = x @ W_in   (4096 x 2048, K=512)
    mma_gemm<128,128,4,2,0><<<dim3(2*DINNER/128, NROWS/128), 256, SMG>>>(
        x, DMODEL, W_in, 2*DINNER, nullptr, nullptr, xz, 2*DINNER, DMODEL);

    // 1) fused conv+silu+xproj
    xproj_conv_kernel<<<NROWS/64, 128>>>(conv_w, conv_b, W_xprj);

    // 2) dt = softplus(dtr @ W_dt + b_dt)   (K=32)
    mma_gemm<128,128,4,2,2><<<dim3(DINNER/128, NROWS/128), 256, SMG>>>(
        dbl, DBLC, W_dt, DINNER, nullptr, b_dt, dt, DINNER, DTRANK);

    // 3) chunked scan pass 1  (launch index 3 -> ncu capture target)
    scan_part1<<<(BSZ*NCH*DINNER*4)/128, 128>>>(A_log);

    // 4) combine + correction + gating
    scan_part3<<<(BSZ*NCH*DINNER*4)/128, 128>>>(A_log, Dvec);

    // 5) h2 = y @ W_out + x
    mma_gemm<128,128,4,2,1><<<dim3(DMODEL/128, NROWS/128), 256, SMG>>>(
        y, DINNER, W_out, DMODEL, x, nullptr, out, DMODEL, DINNER);

    // 6) LayerNorm
    ln_kernel<<<NROWS, 256>>>(out, gamma, beta);
}

// round 17
// speedup vs baseline: 1.8730x; 1.4146x over previous
#include <cuda_runtime.h>
#include <math.h>
#include <stdint.h>

#define BSZ    2
#define LSEQ   2048
#define DMODEL 512
#define DINNER 1024
#define DSTATE 16
#define DTRANK 32
#define DCONV  4
#define NROWS  (BSZ*LSEQ)          // 4096
#define DBLC   (DTRANK + 2*DSTATE) // 64
#define NCH    16
#define CL     (LSEQ/NCH)          // 128

// ---------------- scratch (device globals; no allocs allowed) ----------------
__device__ float g_xz  [NROWS * 2 * DINNER];
__device__ float g_xc  [NROWS * DINNER];
__device__ float g_dbl [NROWS * DBLC];
__device__ float g_dt  [NROWS * DINNER];
__device__ float g_y   [NROWS * DINNER];
__device__ float g_hend[BSZ*NCH*DINNER*DSTATE];
__device__ float g_pend[BSZ*NCH*DINNER*DSTATE];

__device__ __forceinline__ float f2tf32(float x) {
    uint32_t u;
    asm("cvt.rna.tf32.f32 %0, %1;" : "=r"(u) : "f"(x));
    return __uint_as_float(u);
}

__device__ __forceinline__ void mma_tf32(float c[4], const uint32_t a[4],
                                         const uint32_t b[2]) {
    asm volatile(
        "mma.sync.aligned.m16n8k8.row.col.f32.tf32.tf32.f32 "
        "{%0,%1,%2,%3}, {%4,%5,%6,%7}, {%8,%9}, {%0,%1,%2,%3};"
        : "+f"(c[0]), "+f"(c[1]), "+f"(c[2]), "+f"(c[3])
        : "r"(a[0]), "r"(a[1]), "r"(a[2]), "r"(a[3]), "r"(b[0]), "r"(b[1]));
}

__device__ __forceinline__ void cp_async16(uint32_t dst, const void* src) {
    asm volatile("cp.async.cg.shared.global [%0], [%1], 16;" :: "r"(dst), "l"(src));
}
#define CP_COMMIT() asm volatile("cp.async.commit_group;" ::: "memory")
#define CP_WAIT1()  asm volatile("cp.async.wait_group 1;"  ::: "memory")
#define CP_WAIT0()  asm volatile("cp.async.wait_group 0;"  ::: "memory")

// XOR swizzle used by the fused xproj kernel (unchanged, verified).
template<int LD>
__device__ __forceinline__ int swz(int c, int m) {
    return c*LD + (m ^ ((c & 3) << 3) ^ (((c >> 2) & 7) << 2));
}

// ---------------------------------------------------------------------------
// 3-stage cp.async TF32 warp-MMA GEMM, BK=32. (unchanged from 497us kernel)
// ---------------------------------------------------------------------------
template<int BM, int BN, int WARPS_M, int WARPS_N, int MODE>
__global__ void __launch_bounds__(WARPS_M*WARPS_N*32, 2)
mma_gemm(const float* __restrict__ A, int lda,
         const float* __restrict__ W, int ldb,
         const float* __restrict__ RES,
         const float* __restrict__ bias,
         float* __restrict__ C, int N, int K)
{
    constexpr int BK  = 32;
    constexpr int LDA = BK + 4;      // 36
    constexpr int LDB = BN + 8;      // 136
    constexpr int THREADS = WARPS_M*WARPS_N*32;
    constexpr int WM = BM/WARPS_M, WN = BN/WARPS_N;
    constexpr int MT = WM/16, NT = WN/8;
    constexpr int A_CH = (BM*(BK/4)) / THREADS;
    constexpr int B_CH = ((BK*BN)/4) / THREADS;
    constexpr int STG  = BM*LDA + BK*LDB;

    extern __shared__ float sm[];

    const int tid  = threadIdx.x;
    const int wid  = tid >> 5;
    const int lane = tid & 31;
    const int g    = lane >> 2;
    const int q    = lane & 3;
    const int wm0  = (wid % WARPS_M) * WM;
    const int wn0  = (wid / WARPS_M) * WN;
    const int bm   = blockIdx.y * BM;
    const int bn   = blockIdx.x * BN;

    const uint32_t smb = (uint32_t)__cvta_generic_to_shared(sm);

    float acc[MT][NT][4];
    #pragma unroll
    for (int i = 0; i < MT; i++)
        #pragma unroll
        for (int j = 0; j < NT; j++)
            #pragma unroll
            for (int v = 0; v < 4; v++) acc[i][j][v] = 0.f;

    const int nK = K / BK;

    auto load_tile = [&](int stage, int kb) {
        uint32_t base = smb + (uint32_t)(stage*STG)*4;
        int k0 = kb*BK;
        #pragma unroll
        for (int i = 0; i < A_CH; i++) {
            int idx = tid + i*THREADS;
            int r = idx >> 3, c4 = idx & 7;
            cp_async16(base + (uint32_t)(r*LDA + c4*4)*4,
                       A + (long)(bm + r)*lda + k0 + c4*4);
        }
        base += (uint32_t)(BM*LDA)*4;
        #pragma unroll
        for (int i = 0; i < B_CH; i++) {
            int idx = tid + i*THREADS;
            int kr = idx / (BN/4), nc4 = idx % (BN/4);
            cp_async16(base + (uint32_t)(kr*LDB + nc4*4)*4,
                       W + (long)(k0 + kr)*ldb + bn + nc4*4);
        }
        CP_COMMIT();
    };

    load_tile(0, 0);
    if (nK > 1) load_tile(1, 1); else CP_COMMIT();

    for (int kb = 0; kb < nK; kb++) {
        CP_WAIT1();
        __syncthreads();
        if (kb + 2 < nK) load_tile((kb + 2) % 3, kb + 2);
        else CP_COMMIT();

        const float* As = sm + (kb % 3)*STG;
        const float* Bs = As + BM*LDA;

        #pragma unroll
        for (int kk = 0; kk < BK/8; kk++) {
            const int kbk = kk*8;
            uint32_t ah[MT][4], bh[NT][2];
            #pragma unroll
            for (int i = 0; i < MT; i++) {
                int m0 = wm0 + i*16 + g;
                ah[i][0] = __float_as_uint(As[(m0    )*LDA + kbk + q    ]);
                ah[i][1] = __float_as_uint(As[(m0 + 8)*LDA + kbk + q    ]);
                ah[i][2] = __float_as_uint(As[(m0    )*LDA + kbk + q + 4]);
                ah[i][3] = __float_as_uint(As[(m0 + 8)*LDA + kbk + q + 4]);
            }
            #pragma unroll
            for (int j = 0; j < NT; j++) {
                int n0 = wn0 + j*8 + g;
                bh[j][0] = __float_as_uint(Bs[(kbk + q    )*LDB + n0]);
                bh[j][1] = __float_as_uint(Bs[(kbk + q + 4)*LDB + n0]);
            }
            #pragma unroll
            for (int i = 0; i < MT; i++)
                #pragma unroll
                for (int j = 0; j < NT; j++)
                    mma_tf32(acc[i][j], ah[i], bh[j]);
        }
        __syncthreads();
    }
    CP_WAIT0();

    #pragma unroll
    for (int i = 0; i < MT; i++) {
        #pragma unroll
        for (int half = 0; half < 2; half++) {
            int row = bm + wm0 + i*16 + g + half*8;
            #pragma unroll
            for (int j = 0; j < NT; j++) {
                int col = bn + wn0 + j*8 + 2*q;
                float v0 = acc[i][j][half*2 + 0];
                float v1 = acc[i][j][half*2 + 1];
                long base = (long)row*N + col;
                if (MODE == 1) {
                    v0 += RES[base]; v1 += RES[base + 1];
                } else if (MODE == 2) {
                    v0 += bias[col]; v1 += bias[col + 1];
                    v0 = (v0 > 20.f) ? v0 : log1pf(expf(v0));
                    v1 = (v1 > 20.f) ? v1 : log1pf(expf(v1));
                }
                *(float2*)(C + base) = make_float2(v0, v1);
            }
        }
    }
}

// ---------------------------------------------------------------------------
// Fused conv+silu+xproj (unchanged, verified).
// ---------------------------------------------------------------------------
__global__ void __launch_bounds__(128)
xproj_conv_kernel(const float* __restrict__ conv_w,
                  const float* __restrict__ conv_b,
                  const float* __restrict__ Wx)
{
    constexpr int BM = 64, BN = 64, BK = 32;
    constexpr int MT = 2, NT = 4;

    __shared__ float As[BK*BM];
    __shared__ float Bs[BK*BN];

    const int tid  = threadIdx.x;
    const int wid  = tid >> 5;
    const int lane = tid & 31;
    const int g    = lane >> 2;
    const int q    = lane & 3;
    const int wm0  = (wid & 1) * 32;
    const int wn0  = (wid >> 1) * 32;
    const int bm   = blockIdx.x * BM;

    float acc[MT][NT][4];
    #pragma unroll
    for (int i = 0; i < MT; i++)
        #pragma unroll
        for (int j = 0; j < NT; j++)
            #pragma unroll
            for (int v = 0; v < 4; v++) acc[i][j][v] = 0.f;

    for (int k0 = 0; k0 < DINNER; k0 += BK) {
        #pragma unroll
        for (int i = 0; i < 4; i++) {
            int idx = tid + i*128;
            int r = idx >> 3, c4 = idx & 7;
            int m = bm + r;
            int l = m & (LSEQ - 1);
            int k = k0 + c4*4;

            float tv[4][4];
            #pragma unroll
            for (int j = 0; j < 4; j++) {
                float4 t = make_float4(0.f, 0.f, 0.f, 0.f);
                if (l - 3 + j >= 0)
                    t = *(const float4*)(g_xz + (long)(m - 3 + j)*(2*DINNER) + k);
                tv[j][0] = t.x; tv[j][1] = t.y; tv[j][2] = t.z; tv[j][3] = t.w;
            }
            float4 cb = *(const float4*)(conv_b + k);
            float cbv[4] = {cb.x, cb.y, cb.z, cb.w};
            float xo[4];
            #pragma unroll
            for (int cc = 0; cc < 4; cc++) {
                float4 w = *(const float4*)(conv_w + (k + cc)*DCONV);
                float a = cbv[cc] + w.x*tv[0][cc] + w.y*tv[1][cc]
                                  + w.z*tv[2][cc] + w.w*tv[3][cc];
                float sig = 1.f / (1.f + __expf(-a));
                xo[cc] = a * sig;
                As[swz<BM>(c4*4 + cc, r)] = f2tf32(xo[cc]);
            }
            *(float4*)(g_xc + (long)m*DINNER + k) =
                make_float4(xo[0], xo[1], xo[2], xo[3]);
        }
        #pragma unroll
        for (int i = 0; i < 4; i++) {
            int idx = tid + i*128;
            int kr = idx >> 4, nc4 = idx & 15;
            float4 v = *(const float4*)(Wx + (long)(k0 + kr)*DBLC + nc4*4);
            float4 t;
            t.x = f2tf32(v.x); t.y = f2tf32(v.y);
            t.z = f2tf32(v.z); t.w = f2tf32(v.w);
            *(float4*)(Bs + swz<BN>(kr, nc4*4)) = t;
        }
        __syncthreads();

        #pragma unroll
        for (int kk = 0; kk < 4; kk++) {
            const int kb = kk*8;
            uint32_t ah[MT][4], bh[NT][2];
            #pragma unroll
            for (int i = 0; i < MT; i++) {
                int m0 = wm0 + i*16 + g;
                ah[i][0] = __float_as_uint(As[swz<BM>(kb+q,   m0    )]);
                ah[i][1] = __float_as_uint(As[swz<BM>(kb+q,   m0 + 8)]);
                ah[i][2] = __float_as_uint(As[swz<BM>(kb+q+4, m0    )]);
                ah[i][3] = __float_as_uint(As[swz<BM>(kb+q+4, m0 + 8)]);
            }
            #pragma unroll
            for (int j = 0; j < NT; j++) {
                int n0 = wn0 + j*8 + g;
                bh[j][0] = __float_as_uint(Bs[swz<BN>(kb+q,   n0)]);
                bh[j][1] = __float_as_uint(Bs[swz<BN>(kb+q+4, n0)]);
            }
            #pragma unroll
            for (int i = 0; i < MT; i++)
                #pragma unroll
                for (int j = 0; j < NT; j++)
                    mma_tf32(acc[i][j], ah[i], bh[j]);
        }
        __syncthreads();
    }

    #pragma unroll
    for (int i = 0; i < MT; i++) {
        #pragma unroll
        for (int half = 0; half < 2; half++) {
            int row = bm + wm0 + i*16 + g + half*8;
            #pragma unroll
            for (int j = 0; j < NT; j++) {
                int col = wn0 + j*8 + 2*q;
                *(float2*)(g_dbl + (long)row*DBLC + col) =
                    make_float2(acc[i][j][half*2 + 0], acc[i][j][half*2 + 1]);
            }
        }
    }
}

// ---------------------------------------------------------------------------
// Chunked scan, 4 states/thread, NCH=16, software-prefetched groups.
// gid -> j=gid&3 (states 4j..4j+3), d=(gid>>2)&1023, ch=(gid>>12)&15, b=gid>>16.
// ---------------------------------------------------------------------------
__global__ void __launch_bounds__(128) scan_part1(const float* __restrict__ A_log)
{
    int gid = blockIdx.x * 128 + threadIdx.x;
    int j  = gid & 3;
    int d  = (gid >> 2) & 1023;
    int ch = (gid >> 12) & (NCH - 1);
    int b  = gid >> 16;
    int s0 = 4*j;

    float Aa[4], h[4], P[4];
    #pragma unroll
    for (int i = 0; i < 4; i++) {
        Aa[i] = -expf(A_log[d*DSTATE + s0 + i]);
        h[i] = 0.f; P[i] = 1.f;
    }

    long r0 = (long)(b*LSEQ + ch*CL);
    const float* pdt = g_dt  + r0*DINNER + d;
    const float* pxc = g_xc  + r0*DINNER + d;
    const float* pB  = g_dbl + r0*DBLC + DTRANK + s0;
    const float* pC  = pB + DSTATE;
    float*       py  = g_y   + r0*DINNER + d;

    float dtv[4], xv[4];
    float4 Bv[4], Cv[4];
    #pragma unroll
    for (int u = 0; u < 4; u++) {
        dtv[u] = pdt[u*DINNER];
        xv [u] = pxc[u*DINNER];
        Bv [u] = *(const float4*)(pB + u*DBLC);
        Cv [u] = *(const float4*)(pC + u*DBLC);
    }

    for (int t0 = 0; t0 < CL; t0 += 4) {
        float ndt[4], nxv[4];
        float4 nBv[4], nCv[4];
        if (t0 + 4 < CL) {
            #pragma unroll
            for (int u = 0; u < 4; u++) {
                ndt[u] = pdt[(u+4)*DINNER];
                nxv[u] = pxc[(u+4)*DINNER];
                nBv[u] = *(const float4*)(pB + (u+4)*DBLC);
                nCv[u] = *(const float4*)(pC + (u+4)*DBLC);
            }
        }

        float p[4];
        #pragma unroll
        for (int u = 0; u < 4; u++) {
            float qv = dtv[u] * xv[u];
            float dA0 = __expf(dtv[u]*Aa[0]);
            float dA1 = __expf(dtv[u]*Aa[1]);
            float dA2 = __expf(dtv[u]*Aa[2]);
            float dA3 = __expf(dtv[u]*Aa[3]);
            h[0] = h[0]*dA0 + qv*Bv[u].x;  P[0] *= dA0;
            h[1] = h[1]*dA1 + qv*Bv[u].y;  P[1] *= dA1;
            h[2] = h[2]*dA2 + qv*Bv[u].z;  P[2] *= dA2;
            h[3] = h[3]*dA3 + qv*Bv[u].w;  P[3] *= dA3;
            p[u] = h[0]*Cv[u].x + h[1]*Cv[u].y + h[2]*Cv[u].z + h[3]*Cv[u].w;
        }
        #pragma unroll
        for (int u = 0; u < 4; u++) {
            p[u] += __shfl_xor_sync(0xffffffffu, p[u], 2);
            p[u] += __shfl_xor_sync(0xffffffffu, p[u], 1);
        }
        if (j == 0) {
            #pragma unroll
            for (int u = 0; u < 4; u++) py[u*DINNER] = p[u];
        }
        #pragma unroll
        for (int u = 0; u < 4; u++) {
            dtv[u] = ndt[u]; xv[u] = nxv[u]; Bv[u] = nBv[u]; Cv[u] = nCv[u];
        }
        pdt += 4*DINNER; pxc += 4*DINNER; pB += 4*DBLC; pC += 4*DBLC; py += 4*DINNER;
    }
    long idx = ((long)((b*NCH + ch)*DINNER + d))*DSTATE + s0;
    *(float4*)(g_hend + idx) = make_float4(h[0], h[1], h[2], h[3]);
    *(float4*)(g_pend + idx) = make_float4(P[0], P[1], P[2], P[3]);
}

__global__ void __launch_bounds__(128) scan_part3(const float* __restrict__ A_log,
                                                  const float* __restrict__ Dvec)
{
    int gid = blockIdx.x * 128 + threadIdx.x;
    int j  = gid & 3;
    int d  = (gid >> 2) & 1023;
    int ch = (gid >> 12) & (NCH - 1);
    int b  = gid >> 16;
    int s0 = 4*j;

    float Aa[4];
    #pragma unroll
    for (int i = 0; i < 4; i++)
        Aa[i] = -expf(A_log[d*DSTATE + s0 + i]);
    const float Dv = Dvec[d];

    float hin[4] = {0.f, 0.f, 0.f, 0.f};
    for (int c = 0; c < ch; c++) {
        long idx = ((long)((b*NCH + c)*DINNER + d))*DSTATE + s0;
        float4 pe = *(const float4*)(g_pend + idx);
        float4 he = *(const float4*)(g_hend + idx);
        hin[0] = pe.x*hin[0] + he.x;
        hin[1] = pe.y*hin[1] + he.y;
        hin[2] = pe.z*hin[2] + he.z;
        hin[3] = pe.w*hin[3] + he.w;
    }

    long r0 = (long)(b*LSEQ + ch*CL);
    const float* pdt = g_dt  + r0*DINNER + d;
    const float* pxc = g_xc  + r0*DINNER + d;
    const float* pC  = g_dbl + r0*DBLC + DTRANK + DSTATE + s0;
    const float* pz  = g_xz  + r0*(2*DINNER) + DINNER + d;
    float*       py  = g_y   + r0*DINNER + d;

    float dtv[4];
    float4 Cv[4];
    #pragma unroll
    for (int u = 0; u < 4; u++) {
        dtv[u] = pdt[u*DINNER];
        Cv [u] = *(const float4*)(pC + u*DBLC);
    }

    float P[4] = {1.f, 1.f, 1.f, 1.f};
    for (int t0 = 0; t0 < CL; t0 += 4) {
        float ndt[4];
        float4 nCv[4];
        if (t0 + 4 < CL) {
            #pragma unroll
            for (int u = 0; u < 4; u++) {
                ndt[u] = pdt[(u+4)*DINNER];
                nCv[u] = *(const float4*)(pC + (u+4)*DBLC);
            }
        }

        float p[4];
        #pragma unroll
        for (int u = 0; u < 4; u++) {
            P[0] *= __expf(dtv[u]*Aa[0]);
            P[1] *= __expf(dtv[u]*Aa[1]);
            P[2] *= __expf(dtv[u]*Aa[2]);
            P[3] *= __expf(dtv[u]*Aa[3]);
            p[u] = (P[0]*hin[0])*Cv[u].x + (P[1]*hin[1])*Cv[u].y
                 + (P[2]*hin[2])*Cv[u].z + (P[3]*hin[3])*Cv[u].w;
        }
        #pragma unroll
        for (int u = 0; u < 4; u++) {
            p[u] += __shfl_xor_sync(0xffffffffu, p[u], 2);
            p[u] += __shfl_xor_sync(0xffffffffu, p[u], 1);
        }
        if (j == 0) {
            #pragma unroll
            for (int u = 0; u < 4; u++) {
                float y  = py[u*DINNER] + p[u];
                float xv = pxc[u*DINNER];
                float zv = pz [u*2*DINNER];
                float sig = 1.f / (1.f + __expf(-zv));
                py[u*DINNER] = (y + xv*Dv) * (zv * sig);
            }
        }
        #pragma unroll
        for (int u = 0; u < 4; u++) { dtv[u] = ndt[u]; Cv[u] = nCv[u]; }
        pdt += 4*DINNER; pxc += 4*DINNER; pC += 4*DBLC;
        pz  += 4*2*DINNER; py += 4*DINNER;
    }
}

// ---------------------------------------------------------------------------
// LayerNorm over rows of 512 (in-place)
// ---------------------------------------------------------------------------
__global__ void ln_kernel(float* __restrict__ out,
                          const float* __restrict__ gamma,
                          const float* __restrict__ beta)
{
    int row = blockIdx.x;
    int t   = threadIdx.x;
    float v0 = out[(long)row*DMODEL + t];
    float v1 = out[(long)row*DMODEL + 256 + t];

    float s = v0 + v1;
    float qq = v0*v0 + v1*v1;
    #pragma unroll
    for (int o = 16; o; o >>= 1) {
        s  += __shfl_xor_sync(0xffffffffu, s, o);
        qq += __shfl_xor_sync(0xffffffffu, qq, o);
    }
    __shared__ float s1[8], s2[8];
    int wid = t >> 5, lane = t & 31;
    if (lane == 0) { s1[wid] = s; s2[wid] = qq; }
    __syncthreads();
    if (t == 0) {
        float ts = 0.f, tq = 0.f;
        #pragma unroll
        for (int i = 0; i < 8; i++) { ts += s1[i]; tq += s2[i]; }
        float mu = ts / DMODEL;
        s1[0] = mu;
        s2[0] = tq / DMODEL - mu*mu;
    }
    __syncthreads();
    float mu  = s1[0];
    float inv = rsqrtf(s2[0] + 1e-5f);
    out[(long)row*DMODEL + t]       = (v0 - mu) * inv * gamma[t]       + beta[t];
    out[(long)row*DMODEL + 256 + t] = (v1 - mu) * inv * gamma[256 + t] + beta[256 + t];
}

// ---------------------------------------------------------------------------
extern "C" void kernel_launch(void* const* d_in, const int* in_sizes, int n_in,
                              void* d_out, int out_size)
{
    const float* x      = (const float*)d_in[0];
    const float* W_in   = (const float*)d_in[1];
    const float* conv_w = (const float*)d_in[2];
    const float* conv_b = (const float*)d_in[3];
    const float* W_xprj = (const float*)d_in[4];
    const float* W_dt   = (const float*)d_in[5];
    const float* b_dt   = (const float*)d_in[6];
    const float* A_log  = (const float*)d_in[7];
    const float* Dvec   = (const float*)d_in[8];
    const float* W_out  = (const float*)d_in[9];
    const float* gamma  = (const float*)d_in[10];
    const float* beta   = (const float*)d_in[11];
    float* out = (float*)d_out;

    float *xz, *dbl, *dt, *y;
    cudaGetSymbolAddress((void**)&xz,  g_xz);
    cudaGetSymbolAddress((void**)&dbl, g_dbl);
    cudaGetSymbolAddress((void**)&dt,  g_dt);
    cudaGetSymbolAddress((void**)&y,   g_y);

    // 3 stages x (128*36 + 32*136) floats = 107520 bytes
    const int SMG = 3*(128*36 + 32*136)*4;
    cudaFuncSetAttribute(mma_gemm<128,128,4,2,0>, cudaFuncAttributeMaxDynamicSharedMemorySize, SMG);
    cudaFuncSetAttribute(mma_gemm<128,128,4,2,1>, cudaFuncAttributeMaxDynamicSharedMemorySize, SMG);
    cudaFuncSetAttribute(mma_gemm<128,128,4,2,2>, cudaFuncAttributeMaxDynamicSharedMemorySize, SMG);
    cudaFuncSetAttribute(mma_gemm<128,128,4,2,0>, cudaFuncAttributePreferredSharedMemoryCarveout, 100);
    cudaFuncSetAttribute(mma_gemm<128,128,4,2,1>, cudaFuncAttributePreferredSharedMemoryCarveout, 100);
    cudaFuncSetAttribute(mma_gemm<128,128,4,2,2>, cudaFuncAttributePreferredSharedMemoryCarveout, 100);

    // 0) xz = x @ W_in   (4096 x 2048, K=512)
    mma_gemm<128,128,4,2,0><<<dim3(2*DINNER/128, NROWS/128), 256, SMG>>>(
        x, DMODEL, W_in, 2*DINNER, nullptr, nullptr, xz, 2*DINNER, DMODEL);

    // 1) fused conv+silu+xproj
    xproj_conv_kernel<<<NROWS/64, 128>>>(conv_w, conv_b, W_xprj);

    // 2) dt = softplus(dtr @ W_dt + b_dt)   (K=32)
    mma_gemm<128,128,4,2,2><<<dim3(DINNER/128, NROWS/128), 256, SMG>>>(
        dbl, DBLC, W_dt, DINNER, nullptr, b_dt, dt, DINNER, DTRANK);

    // 3) chunked scan pass 1  (launch index 3 -> ncu capture target)
    scan_part1<<<(BSZ*NCH*DINNER*4)/128, 128>>>(A_log);

    // 4) combine + correction + gating
    scan_part3<<<(BSZ*NCH*DINNER*4)/128, 128>>>(A_log, Dvec);

    // 5) h2 = y @ W_out + x
    mma_gemm<128,128,4,2,1><<<dim3(DMODEL/128, NROWS/128), 256, SMG>>>(
        y, DINNER, W_out, DMODEL, x, nullptr, out, DMODEL, DINNER);

    // 6) LayerNorm
    ln_kernel<<<NROWS, 256>>>(out, gamma, beta);
}